// round 7
// baseline (speedup 1.0000x reference)
#include <cuda_runtime.h>
#include <cuda_fp16.h>
#include <cstdint>
#include <string.h>
#include <math.h>

#define NN 8192
#define KC 64

__device__ double g_within;
__device__ float  g_rowsum[NN];
__device__ float  g_colsum[NN];
__device__ int    g_ids[NN];
__device__ float  g_cnt[KC], g_sx[KC], g_sy[KC], g_ds[KC];
__device__ int    g_maxid;
__device__ __half g_AT[KC * NN];   // A^T fp16 [64][8192]

#define MMA16816(c, a0, a1, a2, a3, b0, b1) \
    asm volatile("mma.sync.aligned.m16n8k16.row.col.f32.f16.f16.f32 " \
        "{%0,%1,%2,%3}, {%4,%5,%6,%7}, {%8,%9}, {%0,%1,%2,%3};" \
        : "+f"((c)[0]), "+f"((c)[1]), "+f"((c)[2]), "+f"((c)[3]) \
        : "r"(a0), "r"(a1), "r"(a2), "r"(a3), "r"(b0), "r"(b1))

__device__ __forceinline__ uint32_t h2u(__half2 v) { uint32_t u; memcpy(&u, &v, 4); return u; }

// ---------------- zero small accumulators ----------------
__global__ void k_zero0() {
    int i = threadIdx.x;
    if (i == 0) { g_within = 0.0; g_maxid = 0; }
    if (i < KC) { g_cnt[i] = 0.f; g_sx[i] = 0.f; g_sy[i] = 0.f; g_ds[i] = 0.f; }
}

// ---------------- prep: zero rows/cols, A->fp16 transpose, argmax+segsums --
__global__ __launch_bounds__(128) void k_prep(const float* __restrict__ A,
                                              const float* __restrict__ pos) {
    __shared__ float scnt[KC], ssx[KC], ssy[KC];
    __shared__ int smax;
    const int t = threadIdx.x;
    if (t < KC) { scnt[t] = 0.f; ssx[t] = 0.f; ssy[t] = 0.f; }
    if (t == 0) smax = 0;
    __syncthreads();

    const int j = blockIdx.x * 128 + t;
    g_rowsum[j] = 0.f;
    g_colsum[j] = 0.f;

    float a[KC];
#pragma unroll
    for (int q = 0; q < 16; q++) {
        float4 v = *(const float4*)(A + (size_t)j * KC + q * 4);
        a[q * 4] = v.x; a[q * 4 + 1] = v.y; a[q * 4 + 2] = v.z; a[q * 4 + 3] = v.w;
    }
    float best = -3.402823466e+38f; int bi = 0;
#pragma unroll
    for (int k = 0; k < KC; k++) {
        if (a[k] > best) { best = a[k]; bi = k; }
        g_AT[k * NN + j] = __float2half_rn(a[k]);
    }
    g_ids[j] = bi;
    atomicAdd(&scnt[bi], 1.0f);
    atomicAdd(&ssx[bi], pos[2 * j]);
    atomicAdd(&ssy[bi], pos[2 * j + 1]);
    atomicMax(&smax, bi);
    __syncthreads();
    if (t < KC && scnt[t] != 0.f) {
        atomicAdd(&g_cnt[t], scnt[t]);
        atomicAdd(&g_sx[t], ssx[t]);
        atomicAdd(&g_sy[t], ssy[t]);
    }
    if (t == 0) atomicMax(&g_maxid, smax);
}

// ---------------- main: one pass over E, direct-fragment MMA ---------------
// grid 256 = 64 row-strips x 4 j-quarters; CTA = 8 warps, warp tile M16 x N64.
// k-permutation: stage j-block J (64 wide); lane c=lane&3 owns j in [16c,16c+16);
// slice ks: fragment k-pos {2c,2c+1} -> j = 16c+4ks+{0,1}, {2c+8,2c+9} -> +{2,3}.
__global__ __launch_bounds__(256, 2)
void k_main(const float* __restrict__ E, const float* __restrict__ A) {
    __shared__ float colsm[2048];
    __shared__ float tmp[2][4096];   // [buf][(w*8+g)*64 + col]
    __shared__ float wsum[8];

    const int tid = threadIdx.x, w = tid >> 5, lane = tid & 31;
    const int g = lane >> 2, c = lane & 3;
    const int strip = blockIdx.x >> 2, jq = blockIdx.x & 3;
    const size_t i0 = (size_t)strip * 128;
    const int j0 = jq * 2048;

    for (int i = tid; i < 2048; i += 256) colsm[i] = 0.f;
    __syncthreads();

    const size_t r0 = i0 + 16 * w + g;   // warp's M16 tile rows
    const size_t r1 = r0 + 8;
    const float* E0 = E + r0 * NN + j0 + 16 * c;
    const float* E1 = E + r1 * NN + j0 + 16 * c;

    float acc[8][4];
#pragma unroll
    for (int np = 0; np < 8; np++)
#pragma unroll
        for (int q = 0; q < 4; q++) acc[np][q] = 0.f;
    float rs0 = 0.f, rs1 = 0.f;

#pragma unroll 1
    for (int s = 0; s < 32; s++) {
        const int J = s * 64;

        // ---- load E fragments (8 x float4 per lane) ----
        float4 e0[4], e1[4];
#pragma unroll
        for (int ks = 0; ks < 4; ks++) {
            e0[ks] = *(const float4*)(E0 + J + 4 * ks);
            e1[ks] = *(const float4*)(E1 + J + 4 * ks);
        }

        // ---- row/col sums ----
        float cs[16];
#pragma unroll
        for (int ks = 0; ks < 4; ks++) {
            cs[4 * ks + 0] = e0[ks].x + e1[ks].x;
            cs[4 * ks + 1] = e0[ks].y + e1[ks].y;
            cs[4 * ks + 2] = e0[ks].z + e1[ks].z;
            cs[4 * ks + 3] = e0[ks].w + e1[ks].w;
            rs0 += (e0[ks].x + e0[ks].y) + (e0[ks].z + e0[ks].w);
            rs1 += (e1[ks].x + e1[ks].y) + (e1[ks].z + e1[ks].w);
        }

        // ---- convert to A fragments ----
        uint32_t af[4][4];
#pragma unroll
        for (int ks = 0; ks < 4; ks++) {
            af[ks][0] = h2u(__floats2half2_rn(e0[ks].x, e0[ks].y));
            af[ks][1] = h2u(__floats2half2_rn(e1[ks].x, e1[ks].y));
            af[ks][2] = h2u(__floats2half2_rn(e0[ks].z, e0[ks].w));
            af[ks][3] = h2u(__floats2half2_rn(e1[ks].z, e1[ks].w));
        }

        // ---- colsum partials to smem ----
        float* tb = tmp[s & 1] + (w * 8 + g) * 64 + 16 * c;
        *(float4*)(tb + 0)  = make_float4(cs[0],  cs[1],  cs[2],  cs[3]);
        *(float4*)(tb + 4)  = make_float4(cs[4],  cs[5],  cs[6],  cs[7]);
        *(float4*)(tb + 8)  = make_float4(cs[8],  cs[9],  cs[10], cs[11]);
        *(float4*)(tb + 12) = make_float4(cs[12], cs[13], cs[14], cs[15]);
        __syncthreads();
        if (tid < 64) {
            const float* tp = tmp[s & 1] + tid;
            float acol = 0.f;
#pragma unroll
            for (int u = 0; u < 64; u++) acol += tp[u * 64];
            colsm[J + tid] += acol;
        }

        // ---- B fragments direct from global (fp16) + MMA ----
#pragma unroll
        for (int np = 0; np < 8; np++) {
            const __half* bp = g_AT + (size_t)(8 * np + g) * NN + j0 + J + 16 * c;
            uint4 q0 = *(const uint4*)(bp);
            uint4 q1 = *(const uint4*)(bp + 8);
            MMA16816(acc[np], af[0][0], af[0][1], af[0][2], af[0][3], q0.x, q0.y);
            MMA16816(acc[np], af[1][0], af[1][1], af[1][2], af[1][3], q0.z, q0.w);
            MMA16816(acc[np], af[2][0], af[2][1], af[2][2], af[2][3], q1.x, q1.y);
            MMA16816(acc[np], af[3][0], af[3][1], af[3][2], af[3][3], q1.z, q1.w);
        }
    }

    // ---- rowsum: reduce over c (lane bits 0,1) ----
    rs0 += __shfl_xor_sync(~0u, rs0, 1); rs0 += __shfl_xor_sync(~0u, rs0, 2);
    rs1 += __shfl_xor_sync(~0u, rs1, 1); rs1 += __shfl_xor_sync(~0u, rs1, 2);
    if (c == 0) {
        atomicAdd(&g_rowsum[r0], rs0);
        atomicAdd(&g_rowsum[r1], rs1);
    }
    __syncthreads();
    for (int i = tid; i < 2048; i += 256) atomicAdd(&g_colsum[j0 + i], colsm[i]);

    // ---- within epilogue: dot acc with exact fp32 A ----
    // acc[np]: rows r0 (c0,c1) / r1 (c2,c3); cols 8np + 2c + {0,1}
    {
        float part = 0.f;
#pragma unroll
        for (int np = 0; np < 8; np++) {
            float2 au = *(const float2*)(A + r0 * KC + 8 * np + 2 * c);
            float2 ad = *(const float2*)(A + r1 * KC + 8 * np + 2 * c);
            part += acc[np][0] * au.x + acc[np][1] * au.y
                  + acc[np][2] * ad.x + acc[np][3] * ad.y;
        }
#pragma unroll
        for (int o = 16; o > 0; o >>= 1) part += __shfl_xor_sync(~0u, part, o);
        if (lane == 0) wsum[w] = part;
        __syncthreads();
        if (tid == 0) {
            float sum = 0.f;
#pragma unroll
            for (int u = 0; u < 8; u++) sum += wsum[u];
            atomicAdd(&g_within, (double)sum);
        }
    }
}

// ---------------- spatial pass 2 ----------------
__global__ __launch_bounds__(256) void k_spatial2(const float* __restrict__ pos) {
    __shared__ float sds[KC];
    int t = threadIdx.x;
    if (t < KC) sds[t] = 0.f;
    __syncthreads();
    int i = blockIdx.x * 256 + t;
    int cl = g_ids[i];
    float cnt = g_cnt[cl] + 1e-6f;
    float dx = pos[2 * i] - g_sx[cl] / cnt;
    float dy = pos[2 * i + 1] - g_sy[cl] / cnt;
    atomicAdd(&sds[cl], sqrtf(dx * dx + dy * dy));
    __syncthreads();
    if (t < KC && sds[t] != 0.f) atomicAdd(&g_ds[t], sds[t]);
}

// ---------------- finalize ----------------
__global__ __launch_bounds__(1024) void k_final(const float* __restrict__ cons,
                                                const float* __restrict__ gen,
                                                float* __restrict__ out) {
    double bal = 0.0, se = 0.0;
    for (int i = threadIdx.x; i < NN; i += 1024) {
        float ni = g_colsum[i] - g_rowsum[i];
        float imb = (cons[i] - gen[i]) - ni;
        bal += (double)imb * (double)imb;
        se  += (double)g_rowsum[i];
    }
#pragma unroll
    for (int o = 16; o > 0; o >>= 1) {
        bal += __shfl_xor_sync(~0u, bal, o);
        se  += __shfl_xor_sync(~0u, se, o);
    }
    __shared__ double sbv[32], ssv[32];
    if ((threadIdx.x & 31) == 0) { sbv[threadIdx.x >> 5] = bal; ssv[threadIdx.x >> 5] = se; }
    __syncthreads();
    if (threadIdx.x == 0) {
        double B = 0.0, S = 0.0;
#pragma unroll
        for (int u = 0; u < 32; u++) { B += sbv[u]; S += ssv[u]; }
        float balance = (float)(B / (double)NN);
        float tot = 0.f;
        for (int k = 0; k < KC; k++)
            if (g_cnt[k] >= 2.0f) tot += g_ds[k] / (g_cnt[k] + 1e-6f);
        float spatial = tot / ((float)g_maxid + 1.0f + 1e-6f);
        double clustering = (S - 2.0 * g_within) / ((double)NN * (double)NN + 1e-6);
        out[0] = 1.0f * balance + 0.5f * spatial + 0.3f * (float)clustering;
        out[1] = balance;
        out[2] = spatial;
        out[3] = (float)clustering;
    }
}

extern "C" void kernel_launch(void* const* d_in, const int* in_sizes, int n_in,
                              void* d_out, int out_size) {
    const float* E    = (const float*)d_in[0];
    const float* A    = (const float*)d_in[1];
    const float* pos  = (const float*)d_in[2];
    const float* cons = (const float*)d_in[3];
    const float* gen  = (const float*)d_in[4];
    float* out = (float*)d_out;

    k_zero0<<<1, 256>>>();
    k_prep<<<64, 128>>>(A, pos);
    k_main<<<256, 256>>>(E, A);
    k_spatial2<<<32, 256>>>(pos);
    k_final<<<1, 1024>>>(cons, gen, out);
}

// round 8
// speedup vs baseline: 1.6682x; 1.6682x over previous
#include <cuda_runtime.h>
#include <cuda_fp16.h>
#include <cstdint>
#include <string.h>
#include <math.h>

#define NN 8192
#define KC 64
#define JRANGE 2048
#define JSTEP 64
#define NSTAGE (JRANGE/JSTEP)

__device__ double g_within;
__device__ float  g_rowsum[NN];
__device__ float  g_colsum[NN];
__device__ int    g_ids[NN];
__device__ float  g_cnt[KC], g_sx[KC], g_sy[KC], g_ds[KC];
__device__ int    g_maxid;
__device__ __half g_AT[KC * NN];   // A^T fp16 [64][8192]

__device__ __forceinline__ uint32_t smem_u32(const void* p) {
    uint32_t a;
    asm("{ .reg .u64 t; cvta.to.shared.u64 t, %1; cvt.u32.u64 %0, t; }" : "=r"(a) : "l"(p));
    return a;
}
#define LDSM4(r0, r1, r2, r3, a) \
    asm volatile("ldmatrix.sync.aligned.m8n8.x4.shared.b16 {%0,%1,%2,%3}, [%4];" \
        : "=r"(r0), "=r"(r1), "=r"(r2), "=r"(r3) : "r"(a))
#define MMA16816(c, a0, a1, a2, a3, b0, b1) \
    asm volatile("mma.sync.aligned.m16n8k16.row.col.f32.f16.f16.f32 " \
        "{%0,%1,%2,%3}, {%4,%5,%6,%7}, {%8,%9}, {%0,%1,%2,%3};" \
        : "+f"((c)[0]), "+f"((c)[1]), "+f"((c)[2]), "+f"((c)[3]) \
        : "r"(a0), "r"(a1), "r"(a2), "r"(a3), "r"(b0), "r"(b1))

__device__ __forceinline__ uint32_t h2u(__half2 v) { uint32_t u; memcpy(&u, &v, 4); return u; }

// smem layout (k_main dynamic)
#define OFF_COL 0               // 2048 floats = 8KB
#define OFF_TMP 8192            // 2*512 floats = 4KB
#define OFF_BUF 12288
#define BUFSZ   24576           // E fp16 16KB | B fp16 8KB
#define OFF_B   16384
#define SMEM_MAIN (OFF_BUF + 2*BUFSZ)   // 61440

// ---------------- zero small accumulators ----------------
__global__ void k_zero0() {
    int i = threadIdx.x;
    if (i == 0) { g_within = 0.0; g_maxid = 0; }
    if (i < KC) { g_cnt[i] = 0.f; g_sx[i] = 0.f; g_sy[i] = 0.f; g_ds[i] = 0.f; }
}

// ---- fused prep: zero rowsum/colsum, A->fp16 transpose, argmax + segsums ----
__global__ __launch_bounds__(128) void k_prep(const float* __restrict__ A,
                                              const float* __restrict__ pos) {
    __shared__ float scnt[KC], ssx[KC], ssy[KC];
    __shared__ int smax;
    const int t = threadIdx.x;
    if (t < KC) { scnt[t] = 0.f; ssx[t] = 0.f; ssy[t] = 0.f; }
    if (t == 0) smax = 0;
    __syncthreads();

    const int j = blockIdx.x * 128 + t;
    g_rowsum[j] = 0.f;
    g_colsum[j] = 0.f;

    float a[KC];
#pragma unroll
    for (int q = 0; q < 16; q++) {
        float4 v = *(const float4*)(A + (size_t)j * KC + q * 4);
        a[q * 4] = v.x; a[q * 4 + 1] = v.y; a[q * 4 + 2] = v.z; a[q * 4 + 3] = v.w;
    }
    float best = -3.402823466e+38f; int bi = 0;
#pragma unroll
    for (int k = 0; k < KC; k++) {
        if (a[k] > best) { best = a[k]; bi = k; }
        g_AT[k * NN + j] = __float2half_rn(a[k]);
    }
    g_ids[j] = bi;
    atomicAdd(&scnt[bi], 1.0f);
    atomicAdd(&ssx[bi], pos[2 * j]);
    atomicAdd(&ssy[bi], pos[2 * j + 1]);
    atomicMax(&smax, bi);
    __syncthreads();
    if (t < KC && scnt[t] != 0.f) {
        atomicAdd(&g_cnt[t], scnt[t]);
        atomicAdd(&g_sx[t], ssx[t]);
        atomicAdd(&g_sy[t], ssy[t]);
    }
    if (t == 0) atomicMax(&g_maxid, smax);
}

// ---------------- spatial pass 2 (independent of k_main) ----------------
__global__ __launch_bounds__(256) void k_spatial2(const float* __restrict__ pos) {
    __shared__ float sds[KC];
    int t = threadIdx.x;
    if (t < KC) sds[t] = 0.f;
    __syncthreads();
    int i = blockIdx.x * 256 + t;
    int cl = g_ids[i];
    float cnt = g_cnt[cl] + 1e-6f;
    float dx = pos[2 * i] - g_sx[cl] / cnt;
    float dy = pos[2 * i + 1] - g_sy[cl] / cnt;
    atomicAdd(&sds[cl], sqrtf(dx * dx + dy * dy));
    __syncthreads();
    if (t < KC && sds[t] != 0.f) atomicAdd(&g_ds[t], sds[t]);
}

// ---------------- main (round-6 proven version, verbatim) ----------------
__global__ __launch_bounds__(256, 2)
void k_main(const float* __restrict__ E, const float* __restrict__ A) {
    extern __shared__ char smem[];
    const uint32_t sb = smem_u32(smem);
    const int tid = threadIdx.x, warp = tid >> 5, lane = tid & 31;
    const int strip = blockIdx.x >> 2, jq = blockIdx.x & 3;
    const size_t i0 = (size_t)strip * 128;
    const int j0 = jq * JRANGE;

    float* colsm = (float*)(smem + OFF_COL);
    float* tmp   = (float*)(smem + OFF_TMP);
    for (int i = tid; i < JRANGE; i += 256) colsm[i] = 0.f;
    __syncthreads();

    const int c4 = tid & 15, rb = tid >> 4;
    float rows_acc[8];
    float acc[8][4];
#pragma unroll
    for (int p = 0; p < 8; p++) rows_acc[p] = 0.f;
#pragma unroll
    for (int t = 0; t < 8; t++)
#pragma unroll
        for (int q = 0; q < 4; q++) acc[t][q] = 0.f;

    const float* Ebase = E + i0 * NN + j0;
    float4 ev[8]; uint4 bv[2];
#pragma unroll
    for (int p = 0; p < 8; p++)
        ev[p] = *(const float4*)(Ebase + (size_t)(rb + 16 * p) * NN + c4 * 4);
#pragma unroll
    for (int q = 0; q < 2; q++) {
        int g = tid + q * 256, rn = g >> 3, c16 = g & 7;
        bv[q] = *(const uint4*)(g_AT + rn * NN + j0 + c16 * 8);
    }

    const int mw = warp & 3, nw = warp >> 2;

    for (int s = 0; s < NSTAGE; s++) {
        const int b = s & 1;
        char* buf = smem + OFF_BUF + b * BUFSZ;
        const uint32_t bufu = sb + OFF_BUF + b * BUFSZ;

        float cs0 = 0.f, cs1 = 0.f, cs2 = 0.f, cs3 = 0.f;
#pragma unroll
        for (int p = 0; p < 8; p++) {
            cs0 += ev[p].x; cs1 += ev[p].y; cs2 += ev[p].z; cs3 += ev[p].w;
            rows_acc[p] += (ev[p].x + ev[p].y) + (ev[p].z + ev[p].w);
        }
        cs0 += __shfl_xor_sync(~0u, cs0, 16);
        cs1 += __shfl_xor_sync(~0u, cs1, 16);
        cs2 += __shfl_xor_sync(~0u, cs2, 16);
        cs3 += __shfl_xor_sync(~0u, cs3, 16);
        if (lane < 16) {
            float* tw = tmp + (s & 1) * 512 + warp * 64 + c4 * 4;
            tw[0] = cs0; tw[1] = cs1; tw[2] = cs2; tw[3] = cs3;
        }

        uint2 hi8[8];
#pragma unroll
        for (int p = 0; p < 8; p++) {
            hi8[p] = make_uint2(h2u(__floats2half2_rn(ev[p].x, ev[p].y)),
                                h2u(__floats2half2_rn(ev[p].z, ev[p].w)));
        }
#pragma unroll
        for (int p = 0; p < 8; p++) {
            int r = rb + 16 * p;
            uint32_t off = (uint32_t)(r * 128 + c4 * 8);
            off ^= (uint32_t)((r & 7) << 4);
            *(uint2*)(buf + off) = hi8[p];
        }
#pragma unroll
        for (int q = 0; q < 2; q++) {
            int g = tid + q * 256, rn = g >> 3, c16 = g & 7;
            uint32_t off = (uint32_t)(rn * 128 + c16 * 16);
            off ^= (uint32_t)((rn & 7) << 4);
            *(uint4*)(buf + OFF_B + off) = bv[q];
        }

        if (s + 1 < NSTAGE) {
            const int jc = (s + 1) * JSTEP;
#pragma unroll
            for (int p = 0; p < 8; p++)
                ev[p] = *(const float4*)(Ebase + (size_t)(rb + 16 * p) * NN + jc + c4 * 4);
#pragma unroll
            for (int q = 0; q < 2; q++) {
                int g = tid + q * 256, rn = g >> 3, c16 = g & 7;
                bv[q] = *(const uint4*)(g_AT + rn * NN + j0 + jc + c16 * 8);
            }
        }
        __syncthreads();

        if (tid < 64) {
            const float* tr = tmp + (s & 1) * 512 + tid;
            float a = 0.f;
#pragma unroll
            for (int w = 0; w < 8; w++) a += tr[w * 64];
            colsm[s * JSTEP + tid] += a;
        }

        const int arow = lane & 15;
        const uint32_t abyte = (uint32_t)((lane >> 4) << 4);
#pragma unroll
        for (int ks = 0; ks < 4; ks++) {
            uint32_t a0r, a1r, a2r, a3r, a4r, a5r, a6r, a7r;
            {
                uint32_t r0 = (uint32_t)(32 * mw + arow);
                uint32_t off0 = (r0 * 128 + (uint32_t)(ks * 32) + abyte) ^ ((r0 & 7) << 4);
                LDSM4(a0r, a1r, a2r, a3r, bufu + off0);
                uint32_t r1 = r0 + 16;
                uint32_t off1 = (r1 * 128 + (uint32_t)(ks * 32) + abyte) ^ ((r1 & 7) << 4);
                LDSM4(a4r, a5r, a6r, a7r, bufu + off1);
            }
            uint32_t b0, b1, b2, b3, b4, b5, b6, b7;
            {
                uint32_t n0 = (uint32_t)(32 * nw + arow);
                uint32_t off0 = (n0 * 128 + (uint32_t)(ks * 32) + abyte) ^ ((n0 & 7) << 4);
                LDSM4(b0, b1, b2, b3, bufu + OFF_B + off0);
                uint32_t n1 = n0 + 16;
                uint32_t off1 = (n1 * 128 + (uint32_t)(ks * 32) + abyte) ^ ((n1 & 7) << 4);
                LDSM4(b4, b5, b6, b7, bufu + OFF_B + off1);
            }
            MMA16816(acc[0], a0r, a1r, a2r, a3r, b0, b2);
            MMA16816(acc[1], a0r, a1r, a2r, a3r, b1, b3);
            MMA16816(acc[2], a0r, a1r, a2r, a3r, b4, b6);
            MMA16816(acc[3], a0r, a1r, a2r, a3r, b5, b7);
            MMA16816(acc[4], a4r, a5r, a6r, a7r, b0, b2);
            MMA16816(acc[5], a4r, a5r, a6r, a7r, b1, b3);
            MMA16816(acc[6], a4r, a5r, a6r, a7r, b4, b6);
            MMA16816(acc[7], a4r, a5r, a6r, a7r, b5, b7);
        }
    }

#pragma unroll
    for (int p = 0; p < 8; p++) {
        float v = rows_acc[p];
        v += __shfl_xor_sync(~0u, v, 1);
        v += __shfl_xor_sync(~0u, v, 2);
        v += __shfl_xor_sync(~0u, v, 4);
        v += __shfl_xor_sync(~0u, v, 8);
        if (c4 == 0) atomicAdd(&g_rowsum[i0 + rb + 16 * p], v);
    }
    for (int i = tid; i < JRANGE; i += 256) atomicAdd(&g_colsum[j0 + i], colsm[i]);

    {
        float part = 0.f;
        const int crow = lane >> 2, ccol = 2 * (lane & 3);
#pragma unroll
        for (int a = 0; a < 2; a++)
#pragma unroll
            for (int np = 0; np < 2; np++)
#pragma unroll
                for (int h = 0; h < 2; h++) {
                    const float* cp = acc[(a << 2) | (np << 1) | h];
                    size_t ru = i0 + 32 * mw + 16 * a + crow;
                    int col = 32 * nw + 16 * np + 8 * h + ccol;
                    float2 au = *(const float2*)(A + ru * KC + col);
                    float2 ad = *(const float2*)(A + (ru + 8) * KC + col);
                    part += cp[0] * au.x + cp[1] * au.y + cp[2] * ad.x + cp[3] * ad.y;
                }
#pragma unroll
        for (int o = 16; o > 0; o >>= 1) part += __shfl_xor_sync(~0u, part, o);
        __syncthreads();
        if (lane == 0) tmp[warp] = part;
        __syncthreads();
        if (tid == 0) {
            float s = 0.f;
#pragma unroll
            for (int w = 0; w < 8; w++) s += tmp[w];
            atomicAdd(&g_within, (double)s);
        }
    }
}

// ---------------- finalize ----------------
__global__ __launch_bounds__(1024) void k_final(const float* __restrict__ cons,
                                                const float* __restrict__ gen,
                                                float* __restrict__ out) {
    double bal = 0.0, se = 0.0;
    for (int i = threadIdx.x; i < NN; i += 1024) {
        float ni = g_colsum[i] - g_rowsum[i];
        float imb = (cons[i] - gen[i]) - ni;
        bal += (double)imb * (double)imb;
        se  += (double)g_rowsum[i];
    }
#pragma unroll
    for (int o = 16; o > 0; o >>= 1) {
        bal += __shfl_xor_sync(~0u, bal, o);
        se  += __shfl_xor_sync(~0u, se, o);
    }
    __shared__ double sbv[32], ssv[32];
    if ((threadIdx.x & 31) == 0) { sbv[threadIdx.x >> 5] = bal; ssv[threadIdx.x >> 5] = se; }
    __syncthreads();
    if (threadIdx.x == 0) {
        double B = 0.0, S = 0.0;
#pragma unroll
        for (int u = 0; u < 32; u++) { B += sbv[u]; S += ssv[u]; }
        float balance = (float)(B / (double)NN);
        float tot = 0.f;
        for (int k = 0; k < KC; k++)
            if (g_cnt[k] >= 2.0f) tot += g_ds[k] / (g_cnt[k] + 1e-6f);
        float spatial = tot / ((float)g_maxid + 1.0f + 1e-6f);
        double clustering = (S - 2.0 * g_within) / ((double)NN * (double)NN + 1e-6);
        out[0] = 1.0f * balance + 0.5f * spatial + 0.3f * (float)clustering;
        out[1] = balance;
        out[2] = spatial;
        out[3] = (float)clustering;
    }
}

extern "C" void kernel_launch(void* const* d_in, const int* in_sizes, int n_in,
                              void* d_out, int out_size) {
    const float* E    = (const float*)d_in[0];
    const float* A    = (const float*)d_in[1];
    const float* pos  = (const float*)d_in[2];
    const float* cons = (const float*)d_in[3];
    const float* gen  = (const float*)d_in[4];
    float* out = (float*)d_out;

    cudaFuncSetAttribute(k_main, cudaFuncAttributeMaxDynamicSharedMemorySize, SMEM_MAIN);
    // k_main kept at launch index 3 (ncu capture slot)
    k_zero0<<<1, 256>>>();
    k_prep<<<64, 128>>>(A, pos);
    k_spatial2<<<32, 256>>>(pos);
    k_main<<<256, 256, SMEM_MAIN>>>(E, A);
    k_final<<<1, 1024>>>(cons, gen, out);
}